// round 8
// baseline (speedup 1.0000x reference)
#include <cuda_runtime.h>
#include <cuda_fp16.h>
#include <cstdint>

// B=2, N=1024, C=128, H1=128, H2=64
//   aL[b,i,h] = x[b,i]@W1[:C] + b1 ; aR[b,j,h] = x[b,j]@W1[C:]
//   y[b,i,j] = relu(relu(aL_i + aR_j) @ W2 + b2) @ W3 + b3   (j>i else 0)
// R8: fp16 mma m16n8k16, N-SPLIT: 16 warps (512 thr), warp (mh,nh) does
// mt=4 m-tiles x nt=4 n-tiles (half of N). acc 64 regs -> 4 warps/SMSP
// (R7 was latency-bound: occ 12.4%, issue 31.9%, no pipe >45%).

#define Bb 2
#define Nn 1024
#define Cc 128
#define H1 128
#define H2 64

#define TI 32
#define TJ 16
#define NTILES (Bb * 32 * 64)            // 4096

// scratch (device globals; fp16 pairs, k-permuted)
__device__ __align__(16) __half2 g_aLh[Bb * Nn * 64];
__device__ __align__(16) __half2 g_aRh[Bb * Nn * 64];
__device__ __align__(16) __half2 g_W2h[H2 * 64];

// k-pair j (k=2j,2j+1) -> storage slot: within each group of 8 pairs,
// thread q's pairs (q, q+4) land at (2q, 2q+1)  => one LDS.64 per fragment.
__device__ __forceinline__ int slotperm(int j) {
    int jj = j & 7;
    return (j & ~7) | (jj < 4 ? (jj << 1) : (((jj - 4) << 1) | 1));
}

__device__ __forceinline__ uint32_t h2_relu_add(uint32_t x, uint32_t y) {
    __half2 a = *reinterpret_cast<__half2*>(&x);
    __half2 b = *reinterpret_cast<__half2*>(&y);
    __half2 r = __hmax2(__hadd2(a, b), __float2half2_rn(0.f));
    return *reinterpret_cast<uint32_t*>(&r);
}

__device__ __forceinline__ void mma_f16(float c[4], const uint32_t a[4],
                                        uint32_t b0, uint32_t b1) {
    asm volatile(
        "mma.sync.aligned.m16n8k16.row.col.f32.f16.f16.f32 "
        "{%0,%1,%2,%3},{%4,%5,%6,%7},{%8,%9},{%0,%1,%2,%3};"
        : "+f"(c[0]), "+f"(c[1]), "+f"(c[2]), "+f"(c[3])
        : "r"(a[0]), "r"(a[1]), "r"(a[2]), "r"(a[3]), "r"(b0), "r"(b1));
}

// ---------------------------------------------------------------------------
// Combined prep (256 threads/CTA):
//   [0,128)        : aL/aR for 16 token rows per CTA (x staged in smem)
//   [128,144)      : W2 convert (4096 half2)
//   [144,144+2048) : zero-fill output (524288 float4)
// ---------------------------------------------------------------------------
#define ROW_BLKS 128
#define W2_BLKS 16
#define ZERO_BLKS 2048
#define PREP_GRID (ROW_BLKS + W2_BLKS + ZERO_BLKS)

__global__ void __launch_bounds__(256)
prep_kernel(const float* __restrict__ x,
            const float* __restrict__ W1,
            const float* __restrict__ b1,
            const float* __restrict__ W2,
            float4* __restrict__ out4) {
    const int blk = blockIdx.x;
    const int tid = threadIdx.x;

    if (blk < ROW_BLKS) {
        __shared__ float sx[16][Cc];      // 8KB
        __shared__ float res[16][256];    // 16KB: [row][side*128 + h]
        const int r0 = blk * 16;

        {
            const float4* x4 = (const float4*)x;
#pragma unroll
            for (int u = 0; u < 2; u++)
                ((float4*)sx)[tid + 256 * u] = x4[r0 * 32 + tid + 256 * u];
        }
        __syncthreads();

        const int side = tid >> 7;        // 0 = L, 1 = R
        const int h = tid & 127;
        const float* Wp = W1 + (side ? (Cc * H1 + h) : h);   // stride H1
        float acc[16];
        const float init = side ? 0.f : b1[h];
#pragma unroll
        for (int r = 0; r < 16; r++) acc[r] = init;

#pragma unroll 4
        for (int c = 0; c < Cc; c += 4) {
            float w0 = __ldg(&Wp[(c + 0) * H1]);
            float w1 = __ldg(&Wp[(c + 1) * H1]);
            float w2 = __ldg(&Wp[(c + 2) * H1]);
            float w3 = __ldg(&Wp[(c + 3) * H1]);
#pragma unroll
            for (int r = 0; r < 16; r++) {
                float4 sv = *(const float4*)&sx[r][c];
                float a = acc[r];
                a = fmaf(sv.x, w0, a);
                a = fmaf(sv.y, w1, a);
                a = fmaf(sv.z, w2, a);
                a = fmaf(sv.w, w3, a);
                acc[r] = a;
            }
        }
#pragma unroll
        for (int r = 0; r < 16; r++) res[r][side * 128 + h] = acc[r];
        __syncthreads();

#pragma unroll
        for (int u = 0; u < 8; u++) {
            int idx = tid + 256 * u;      // 0..2047
            int row = idx >> 7;
            int rem = idx & 127;
            int sd = rem >> 6;
            int j = rem & 63;
            __half2 v = __floats2half2_rn(res[row][sd * 128 + 2 * j],
                                          res[row][sd * 128 + 2 * j + 1]);
            (sd ? g_aRh : g_aLh)[(size_t)(r0 + row) * 64 + slotperm(j)] = v;
        }
    } else if (blk < ROW_BLKS + W2_BLKS) {
        int idx = (blk - ROW_BLKS) * 256 + tid;   // 0..4095
        int n = idx >> 6;                         // 0..63
        int j = idx & 63;                         // k-pair
        g_W2h[n * 64 + slotperm(j)] =
            __floats2half2_rn(W2[(2 * j) * H2 + n], W2[(2 * j + 1) * H2 + n]);
    } else {
        int i = (blk - ROW_BLKS - W2_BLKS) * 256 + tid;   // 0..524287
        out4[i] = make_float4(0.f, 0.f, 0.f, 0.f);
    }
}

// ---------------------------------------------------------------------------
// Persistent pair kernel. 512 threads = 16 warps. Tile 32i x 16j = 512 pairs.
// Warp (mh = wid&7, nh = wid>>3): m-tiles il = 4mh..4mh+3, n-tiles nh*4..+3.
// ---------------------------------------------------------------------------
#define AR_STRIDE 34     // uint2 per aR row (padded)
#define W2_STRIDE 34     // uint2 per W2 n-row (padded)

struct SmemLayout {
    uint2 w2[H2 * W2_STRIDE];   // 17408 B
    uint2 aL[TI * 32];          //  8192 B (warp-uniform row reads, no pad)
    uint2 aR[TJ * AR_STRIDE];   //  4352 B (reused as partial buffer in epilogue)
    float b2s[H2];
    float w3s[H2];
};

__global__ void __launch_bounds__(512, 1)
pair_kernel(const float* __restrict__ b2,
            const float* __restrict__ W3,
            const float* __restrict__ b3,
            float* __restrict__ out) {
    __shared__ SmemLayout sm;

    const int tid = threadIdx.x;
    const int wid = tid >> 5;      // 0..15
    const int lane = tid & 31;
    const int p = lane >> 2;       // 0..7
    const int q = lane & 3;        // 0..3
    const int mh = wid & 7;        // m-group
    const int nh = wid >> 3;       // n-half (0/1)

    // stage W2 (padded rows) + biases, once
    {
        const uint2* gW2 = (const uint2*)g_W2h;
        for (int i = tid; i < H2 * 32; i += 512) {
            int r = i >> 5, c = i & 31;
            sm.w2[r * W2_STRIDE + c] = gW2[i];
        }
        if (tid < H2) {
            sm.b2s[tid] = b2[tid];
            sm.w3s[tid] = W3[tid];
        }
    }
    const float b3v = __ldg(&b3[0]);
    __syncthreads();

    const int il0 = 4 * mh;
    float* pbuf = (float*)sm.aR;   // 8*4*16 floats = 2KB partial buffer

    for (int t = blockIdx.x; t < NTILES; t += gridDim.x) {
        const int b  = t >> 11;                 // /(32*64)
        const int it = (t >> 6) & 31;
        const int jt = t & 63;
        const int i0 = it * TI;
        const int j0 = jt * TJ;
        if (j0 + TJ - 1 <= i0) continue;        // tile fully at/below diagonal

        // ---- stage aL (32 rows, linear) + aR (16 rows, padded) ----
        {
            const uint2* sL = (const uint2*)(g_aLh + ((size_t)((b << 10) + i0) << 6));
            const uint2* sR = (const uint2*)(g_aRh + ((size_t)((b << 10) + j0) << 6));
#pragma unroll
            for (int u = 0; u < 2; u++)
                sm.aL[tid + 512 * u] = sL[tid + 512 * u];
            {
                int r = tid >> 5, c = tid & 31;
                sm.aR[r * AR_STRIDE + c] = sR[tid];
            }
        }
        __syncthreads();

        float acc[4][4][4];
#pragma unroll
        for (int mt = 0; mt < 4; mt++)
#pragma unroll
            for (int nt = 0; nt < 4; nt++)
#pragma unroll
                for (int e = 0; e < 4; e++) acc[mt][nt][e] = 0.f;

#pragma unroll
        for (int ks = 0; ks < 8; ks++) {
            const int kf = 4 * ks + q;          // uint2 index within row
            uint2 Rp  = sm.aR[p * AR_STRIDE + kf];
            uint2 Rp8 = sm.aR[(p + 8) * AR_STRIDE + kf];

            uint32_t a[4][4];
#pragma unroll
            for (int mt = 0; mt < 4; mt++) {
                uint2 La = sm.aL[(il0 + mt) * 32 + kf];
                a[mt][0] = h2_relu_add(La.x, Rp.x);    // row p,   k 2q..2q+1
                a[mt][1] = h2_relu_add(La.x, Rp8.x);   // row p+8, k 2q..2q+1
                a[mt][2] = h2_relu_add(La.y, Rp.y);    // row p,   k 2q+8..9
                a[mt][3] = h2_relu_add(La.y, Rp8.y);   // row p+8, k 2q+8..9
            }

#pragma unroll
            for (int ntl = 0; ntl < 4; ntl++) {
                int nrow = (nh * 4 + ntl) * 8 + p;
                uint2 bb = sm.w2[nrow * W2_STRIDE + kf];
#pragma unroll
                for (int mt = 0; mt < 4; mt++)
                    mma_f16(acc[mt][ntl], a[mt], bb.x, bb.y);
            }
        }

        // ---- epilogue: partial dot with W3 over this warp's 32 g's ----
        float plo[4], phi[4];
#pragma unroll
        for (int mt = 0; mt < 4; mt++) {
            float slo = 0.f, shi = 0.f;
#pragma unroll
            for (int ntl = 0; ntl < 4; ntl++) {
                int g0 = (nh * 4 + ntl) * 8 + 2 * q;
                float b20 = sm.b2s[g0], b21 = sm.b2s[g0 + 1];
                float w30 = sm.w3s[g0], w31 = sm.w3s[g0 + 1];
                slo = fmaf(fmaxf(acc[mt][ntl][0] + b20, 0.f), w30, slo);
                slo = fmaf(fmaxf(acc[mt][ntl][1] + b21, 0.f), w31, slo);
                shi = fmaf(fmaxf(acc[mt][ntl][2] + b20, 0.f), w30, shi);
                shi = fmaf(fmaxf(acc[mt][ntl][3] + b21, 0.f), w31, shi);
            }
            slo += __shfl_xor_sync(0xFFFFFFFFu, slo, 1);
            slo += __shfl_xor_sync(0xFFFFFFFFu, slo, 2);
            shi += __shfl_xor_sync(0xFFFFFFFFu, shi, 1);
            shi += __shfl_xor_sync(0xFFFFFFFFu, shi, 2);
            plo[mt] = slo;
            phi[mt] = shi;
        }
        __syncthreads();   // aR reads done everywhere; safe to reuse as pbuf

        if (nh == 1 && q == 0) {
#pragma unroll
            for (int mt = 0; mt < 4; mt++) {
                pbuf[(mh * 4 + mt) * 16 + p]     = plo[mt];
                pbuf[(mh * 4 + mt) * 16 + p + 8] = phi[mt];
            }
        }
        __syncthreads();

        if (nh == 0 && q == 0) {
#pragma unroll
            for (int mt = 0; mt < 4; mt++) {
                int gi = i0 + il0 + mt;
                int gjlo = j0 + p;
                int gjhi = gjlo + 8;
                size_t base = ((size_t)((b << 10) + gi)) << 10;
                float ylo = plo[mt] + pbuf[(mh * 4 + mt) * 16 + p] + b3v;
                float yhi = phi[mt] + pbuf[(mh * 4 + mt) * 16 + p + 8] + b3v;
                if (gjlo > gi) out[base + gjlo] = ylo;
                if (gjhi > gi) out[base + gjhi] = yhi;
            }
        }
        __syncthreads();   // protect pbuf/aR before next tile's staging
    }
}

// ---------------------------------------------------------------------------
extern "C" void kernel_launch(void* const* d_in, const int* in_sizes, int n_in,
                              void* d_out, int out_size) {
    const float* x  = (const float*)d_in[0];
    const float* W1 = (const float*)d_in[1];
    const float* b1 = (const float*)d_in[2];
    const float* W2 = (const float*)d_in[3];
    const float* b2 = (const float*)d_in[4];
    const float* W3 = (const float*)d_in[5];
    const float* b3 = (const float*)d_in[6];
    float* out = (float*)d_out;

    prep_kernel<<<PREP_GRID, 256>>>(x, W1, b1, W2, (float4*)out);
    pair_kernel<<<152, 512>>>(b2, W3, b3, out);
}

// round 9
// speedup vs baseline: 1.1890x; 1.1890x over previous
#include <cuda_runtime.h>
#include <cuda_fp16.h>
#include <cstdint>

// B=2, N=1024, C=128, H1=128, H2=64
//   aL[b,i,h] = x[b,i]@W1[:C] + b1 ; aR[b,j,h] = x[b,j]@W1[C:]
//   y[b,i,j] = relu(relu(aL_i + aR_j) @ W2 + b2) @ W3 + b3   (j>i else 0)
// R9 (base = R7: mt=4, nt=8, 256 thr — best at 69.7us):
//  1) analytic active-tile enumeration -> perfect CTA load balance
//  2) W2 frags for nt 0..3 persistent in registers -> W2 LDS halved
//  3) zeroing folded into pair kernel (masked tiles + in-tile zeros);
//     prep loses its 2048 zero-fill CTAs.

#define Bb 2
#define Nn 1024
#define Cc 128
#define H1 128
#define H2 64

#define TI 32
#define TJ 16
#define NACT  2112     // active tiles: 2 * sum_{it<32}(64-2it) = 2*1056
#define NMASK 1984     // fully-masked tiles: 2 * sum_{it<32} 2it = 2*992

// scratch (device globals; fp16 pairs, k-permuted)
__device__ __align__(16) __half2 g_aLh[Bb * Nn * 64];
__device__ __align__(16) __half2 g_aRh[Bb * Nn * 64];
__device__ __align__(16) __half2 g_W2h[H2 * 64];

// k-pair j (k=2j,2j+1) -> storage slot: within each group of 8 pairs,
// thread q's pairs (q, q+4) land at (2q, 2q+1)  => one LDS.64 per fragment.
__device__ __forceinline__ int slotperm(int j) {
    int jj = j & 7;
    return (j & ~7) | (jj < 4 ? (jj << 1) : (((jj - 4) << 1) | 1));
}

__device__ __forceinline__ uint32_t h2_relu_add(uint32_t x, uint32_t y) {
    __half2 a = *reinterpret_cast<__half2*>(&x);
    __half2 b = *reinterpret_cast<__half2*>(&y);
    __half2 r = __hmax2(__hadd2(a, b), __float2half2_rn(0.f));
    return *reinterpret_cast<uint32_t*>(&r);
}

__device__ __forceinline__ void mma_f16(float c[4], const uint32_t a[4],
                                        uint32_t b0, uint32_t b1) {
    asm volatile(
        "mma.sync.aligned.m16n8k16.row.col.f32.f16.f16.f32 "
        "{%0,%1,%2,%3},{%4,%5,%6,%7},{%8,%9},{%0,%1,%2,%3};"
        : "+f"(c[0]), "+f"(c[1]), "+f"(c[2]), "+f"(c[3])
        : "r"(a[0]), "r"(a[1]), "r"(a[2]), "r"(a[3]), "r"(b0), "r"(b1));
}

// ---------------------------------------------------------------------------
// Prep (256 threads/CTA): [0,128) aL/aR rows (16/CTA); [128,144) W2 convert.
// ---------------------------------------------------------------------------
#define ROW_BLKS 128
#define W2_BLKS 16
#define PREP_GRID (ROW_BLKS + W2_BLKS)

__global__ void __launch_bounds__(256)
prep_kernel(const float* __restrict__ x,
            const float* __restrict__ W1,
            const float* __restrict__ b1,
            const float* __restrict__ W2) {
    const int blk = blockIdx.x;
    const int tid = threadIdx.x;

    if (blk < ROW_BLKS) {
        __shared__ float sx[16][Cc];      // 8KB
        __shared__ float res[16][256];    // 16KB: [row][side*128 + h]
        const int r0 = blk * 16;

        {
            const float4* x4 = (const float4*)x;
#pragma unroll
            for (int u = 0; u < 2; u++)
                ((float4*)sx)[tid + 256 * u] = x4[r0 * 32 + tid + 256 * u];
        }
        __syncthreads();

        const int side = tid >> 7;        // 0 = L, 1 = R
        const int h = tid & 127;
        const float* Wp = W1 + (side ? (Cc * H1 + h) : h);   // stride H1
        float acc[16];
        const float init = side ? 0.f : b1[h];
#pragma unroll
        for (int r = 0; r < 16; r++) acc[r] = init;

#pragma unroll 4
        for (int c = 0; c < Cc; c += 4) {
            float w0 = __ldg(&Wp[(c + 0) * H1]);
            float w1 = __ldg(&Wp[(c + 1) * H1]);
            float w2 = __ldg(&Wp[(c + 2) * H1]);
            float w3 = __ldg(&Wp[(c + 3) * H1]);
#pragma unroll
            for (int r = 0; r < 16; r++) {
                float4 sv = *(const float4*)&sx[r][c];
                float a = acc[r];
                a = fmaf(sv.x, w0, a);
                a = fmaf(sv.y, w1, a);
                a = fmaf(sv.z, w2, a);
                a = fmaf(sv.w, w3, a);
                acc[r] = a;
            }
        }
#pragma unroll
        for (int r = 0; r < 16; r++) res[r][side * 128 + h] = acc[r];
        __syncthreads();

#pragma unroll
        for (int u = 0; u < 8; u++) {
            int idx = tid + 256 * u;      // 0..2047
            int row = idx >> 7;
            int rem = idx & 127;
            int sd = rem >> 6;
            int j = rem & 63;
            __half2 v = __floats2half2_rn(res[row][sd * 128 + 2 * j],
                                          res[row][sd * 128 + 2 * j + 1]);
            (sd ? g_aRh : g_aLh)[(size_t)(r0 + row) * 64 + slotperm(j)] = v;
        }
    } else {
        int idx = (blk - ROW_BLKS) * 256 + tid;   // 0..4095
        int n = idx >> 6;                         // 0..63
        int j = idx & 63;                         // k-pair
        g_W2h[n * 64 + slotperm(j)] =
            __floats2half2_rn(W2[(2 * j) * H2 + n], W2[(2 * j + 1) * H2 + n]);
    }
}

// ---------------------------------------------------------------------------
// Persistent pair kernel. 256 threads = 8 warps. Tile 32i x 16j = 512 pairs.
// Warp w owns m-tiles il = 4w..4w+3. nt 0..3 W2 frags live in registers.
// ---------------------------------------------------------------------------
#define AR_STRIDE 34     // uint2 per aR row (padded)
#define W2_STRIDE 34     // uint2 per W2 n-row (padded)

struct SmemLayout {
    uint2 w2[H2 * W2_STRIDE];   // 17408 B
    uint2 aL[TI * 32];          //  8192 B (warp-uniform row reads, no pad)
    uint2 aR[TJ * AR_STRIDE];   //  4352 B
    float b2s[H2];
    float w3s[H2];
};

__global__ void __launch_bounds__(256)
pair_kernel(const float* __restrict__ b2,
            const float* __restrict__ W3,
            const float* __restrict__ b3,
            float* __restrict__ out) {
    __shared__ SmemLayout sm;

    const int tid = threadIdx.x;
    const int wid = tid >> 5;      // 0..7
    const int lane = tid & 31;
    const int p = lane >> 2;       // 0..7
    const int q = lane & 3;        // 0..3

    // stage W2 (padded rows) + biases, once
    {
        const uint2* gW2 = (const uint2*)g_W2h;
        for (int i = tid; i < H2 * 32; i += 256) {
            int r = i >> 5, c = i & 31;
            sm.w2[r * W2_STRIDE + c] = gW2[i];
        }
        if (tid < H2) {
            sm.b2s[tid] = b2[tid];
            sm.w3s[tid] = W3[tid];
        }
    }
    const float b3v = __ldg(&b3[0]);
    __syncthreads();

    // ---- zero fully-masked tiles (overlaps with everything; no races:
    //      masked tiles are never touched by the value path) ----
    {
        float4* out4 = (float4*)out;
        for (int m = blockIdx.x; m < NMASK; m += gridDim.x) {
            int bz = (m >= NMASK / 2);
            int mm = m - (bz ? NMASK / 2 : 0);
            int itz = (int)((1.f + sqrtf(1.f + 4.f * (float)mm)) * 0.5f);
            while (itz * (itz + 1) <= mm) itz++;
            while (itz * (itz - 1) > mm) itz--;
            int jtz = mm - itz * (itz - 1);
            if (tid < 128) {
                int r = tid >> 2, c4 = tid & 3;
                out4[(size_t)((bz << 10) + itz * TI + r) * 256 + jtz * 4 + c4] =
                    make_float4(0.f, 0.f, 0.f, 0.f);
            }
        }
    }

    // ---- persistent W2 fragments for nt 0..3 (64 regs) ----
    uint32_t w2r[8][4][2];
#pragma unroll
    for (int ks = 0; ks < 8; ks++)
#pragma unroll
        for (int ntl = 0; ntl < 4; ntl++) {
            uint2 bb = sm.w2[(ntl * 8 + p) * W2_STRIDE + 4 * ks + q];
            w2r[ks][ntl][0] = bb.x;
            w2r[ks][ntl][1] = bb.y;
        }

    const int il0 = 4 * wid;

    for (int a = blockIdx.x; a < NACT; a += gridDim.x) {
        // decode active tile: b, it, jt (jt >= 2it)
        const int b = (a >= NACT / 2);
        int aa = a - (b ? NACT / 2 : 0);
        int it = (int)((65.f - sqrtf(4225.f - 4.f * (float)aa)) * 0.5f);
        while ((it + 1) * (64 - it) <= aa) it++;     // C(it+1) = (it+1)(65-(it+1))
        while (it * (65 - it) > aa) it--;
        const int jt = 2 * it + (aa - it * (65 - it));
        const int i0 = it * TI;
        const int j0 = jt * TJ;

        // ---- stage aL (32 rows, linear) + aR (16 rows, padded) ----
        {
            const uint2* sL = (const uint2*)(g_aLh + ((size_t)((b << 10) + i0) << 6));
            const uint2* sR = (const uint2*)(g_aRh + ((size_t)((b << 10) + j0) << 6));
#pragma unroll
            for (int u = 0; u < 4; u++)
                sm.aL[tid + 256 * u] = sL[tid + 256 * u];
#pragma unroll
            for (int u = 0; u < 2; u++) {
                int i4 = tid + 256 * u;         // 0..511
                int r = i4 >> 5, c = i4 & 31;
                sm.aR[r * AR_STRIDE + c] = sR[i4];
            }
        }
        __syncthreads();

        float acc[4][8][4];
#pragma unroll
        for (int mt = 0; mt < 4; mt++)
#pragma unroll
            for (int nt = 0; nt < 8; nt++)
#pragma unroll
                for (int e = 0; e < 4; e++) acc[mt][nt][e] = 0.f;

#pragma unroll
        for (int ks = 0; ks < 8; ks++) {
            const int kf = 4 * ks + q;          // uint2 index within row
            uint2 Rp  = sm.aR[p * AR_STRIDE + kf];
            uint2 Rp8 = sm.aR[(p + 8) * AR_STRIDE + kf];

            uint32_t a4[4][4];
#pragma unroll
            for (int mt = 0; mt < 4; mt++) {
                uint2 La = sm.aL[(il0 + mt) * 32 + kf];
                a4[mt][0] = h2_relu_add(La.x, Rp.x);    // row p,   k 2q..2q+1
                a4[mt][1] = h2_relu_add(La.x, Rp8.x);   // row p+8, k 2q..2q+1
                a4[mt][2] = h2_relu_add(La.y, Rp.y);    // row p,   k 2q+8..9
                a4[mt][3] = h2_relu_add(La.y, Rp8.y);   // row p+8, k 2q+8..9
            }

            // nt 0..3 from registers
#pragma unroll
            for (int ntl = 0; ntl < 4; ntl++)
#pragma unroll
                for (int mt = 0; mt < 4; mt++)
                    mma_f16(acc[mt][ntl], a4[mt],
                            w2r[ks][ntl][0], w2r[ks][ntl][1]);
            // nt 4..7 from smem
#pragma unroll
            for (int ntl = 4; ntl < 8; ntl++) {
                uint2 bb = sm.w2[(ntl * 8 + p) * W2_STRIDE + kf];
#pragma unroll
                for (int mt = 0; mt < 4; mt++)
                    mma_f16(acc[mt][ntl], a4[mt], bb.x, bb.y);
            }
        }

        // ---- epilogue: y = b3 + sum_g relu(D+b2)*W3 ; quad reduction ----
        // Unconditional stores: below/at diagonal cells get exact 0
        // (this tile is the unique writer of its 32x16 region).
#pragma unroll
        for (int mt = 0; mt < 4; mt++) {
            float slo = 0.f, shi = 0.f;
#pragma unroll
            for (int nt = 0; nt < 8; nt++) {
                int g0 = nt * 8 + 2 * q;
                float b20 = sm.b2s[g0], b21 = sm.b2s[g0 + 1];
                float w30 = sm.w3s[g0], w31 = sm.w3s[g0 + 1];
                slo = fmaf(fmaxf(acc[mt][nt][0] + b20, 0.f), w30, slo);
                slo = fmaf(fmaxf(acc[mt][nt][1] + b21, 0.f), w31, slo);
                shi = fmaf(fmaxf(acc[mt][nt][2] + b20, 0.f), w30, shi);
                shi = fmaf(fmaxf(acc[mt][nt][3] + b21, 0.f), w31, shi);
            }
            slo += __shfl_xor_sync(0xFFFFFFFFu, slo, 1);
            slo += __shfl_xor_sync(0xFFFFFFFFu, slo, 2);
            shi += __shfl_xor_sync(0xFFFFFFFFu, shi, 1);
            shi += __shfl_xor_sync(0xFFFFFFFFu, shi, 2);
            if (q == 0) {
                int gi = i0 + il0 + mt;
                int gjlo = j0 + p;
                int gjhi = gjlo + 8;
                size_t base = ((size_t)((b << 10) + gi)) << 10;
                out[base + gjlo] = (gjlo > gi) ? (slo + b3v) : 0.f;
                out[base + gjhi] = (gjhi > gi) ? (shi + b3v) : 0.f;
            }
        }
        __syncthreads();   // protect aL/aR before next tile's staging
    }
}

// ---------------------------------------------------------------------------
extern "C" void kernel_launch(void* const* d_in, const int* in_sizes, int n_in,
                              void* d_out, int out_size) {
    const float* x  = (const float*)d_in[0];
    const float* W1 = (const float*)d_in[1];
    const float* b1 = (const float*)d_in[2];
    const float* W2 = (const float*)d_in[3];
    const float* b2 = (const float*)d_in[4];
    const float* W3 = (const float*)d_in[5];
    const float* b3 = (const float*)d_in[6];
    float* out = (float*)d_out;

    prep_kernel<<<PREP_GRID, 256>>>(x, W1, b1, W2);
    pair_kernel<<<152, 256>>>(b2, W3, b3, out);
}

// round 10
// speedup vs baseline: 1.2634x; 1.0625x over previous
#include <cuda_runtime.h>
#include <cuda_fp16.h>
#include <cstdint>

// B=2, N=1024, C=128, H1=128, H2=64
//   aL[b,i,h] = x[b,i]@W1[:C] + b1 ; aR[b,j,h] = x[b,j]@W1[C:]
//   y[b,i,j] = relu(relu(aL_i + aR_j) @ W2 + b2) @ W3 + b3   (j>i else 0)
// R10 (base = R9, 65.9us pair; latency-bound: occ 12.5%, issue 28.6%):
//  1) cp.async double-buffered aL/aR staging (LDG exposure hidden under MMA)
//  2) one-kstep register pipeline of the 6 fragment LDS per kstep
//  (occupancy is reg-capped at 2 warps/SMSP; this round buys overlap instead)

#define Bb 2
#define Nn 1024
#define Cc 128
#define H1 128
#define H2 64

#define TI 32
#define TJ 16
#define NACT  2112     // active tiles: 2 * 1056
#define NMASK 1984     // fully-masked tiles: 2 * 992
#define HALF_ACT 1056

// scratch (device globals; fp16 pairs, k-permuted)
__device__ __align__(16) __half2 g_aLh[Bb * Nn * 64];
__device__ __align__(16) __half2 g_aRh[Bb * Nn * 64];
__device__ __align__(16) __half2 g_W2h[H2 * 64];

// k-pair j (k=2j,2j+1) -> storage slot: within each group of 8 pairs,
// thread q's pairs (q, q+4) land at (2q, 2q+1)  => one LDS.64 per fragment.
__device__ __forceinline__ int slotperm(int j) {
    int jj = j & 7;
    return (j & ~7) | (jj < 4 ? (jj << 1) : (((jj - 4) << 1) | 1));
}

__device__ __forceinline__ uint32_t h2_relu_add(uint32_t x, uint32_t y) {
    __half2 a = *reinterpret_cast<__half2*>(&x);
    __half2 b = *reinterpret_cast<__half2*>(&y);
    __half2 r = __hmax2(__hadd2(a, b), __float2half2_rn(0.f));
    return *reinterpret_cast<uint32_t*>(&r);
}

__device__ __forceinline__ void mma_f16(float c[4], const uint32_t a[4],
                                        uint32_t b0, uint32_t b1) {
    asm volatile(
        "mma.sync.aligned.m16n8k16.row.col.f32.f16.f16.f32 "
        "{%0,%1,%2,%3},{%4,%5,%6,%7},{%8,%9},{%0,%1,%2,%3};"
        : "+f"(c[0]), "+f"(c[1]), "+f"(c[2]), "+f"(c[3])
        : "r"(a[0]), "r"(a[1]), "r"(a[2]), "r"(a[3]), "r"(b0), "r"(b1));
}

__device__ __forceinline__ uint32_t smem_u32(const void* p) {
    uint32_t a;
    asm("{ .reg .u64 t; cvta.to.shared.u64 t, %1; cvt.u32.u64 %0, t; }"
        : "=r"(a) : "l"(p));
    return a;
}
__device__ __forceinline__ void cpasync16(uint32_t dst, const void* src) {
    asm volatile("cp.async.cg.shared.global [%0], [%1], 16;"
                 :: "r"(dst), "l"(src));
}
#define CP_COMMIT() asm volatile("cp.async.commit_group;" ::: "memory")
#define CP_WAIT1()  asm volatile("cp.async.wait_group 1;" ::: "memory")

// ---------------------------------------------------------------------------
// Prep (256 threads/CTA): [0,128) aL/aR rows (16/CTA); [128,144) W2 convert.
// ---------------------------------------------------------------------------
#define ROW_BLKS 128
#define W2_BLKS 16
#define PREP_GRID (ROW_BLKS + W2_BLKS)

__global__ void __launch_bounds__(256)
prep_kernel(const float* __restrict__ x,
            const float* __restrict__ W1,
            const float* __restrict__ b1,
            const float* __restrict__ W2) {
    const int blk = blockIdx.x;
    const int tid = threadIdx.x;

    if (blk < ROW_BLKS) {
        __shared__ float sx[16][Cc];      // 8KB
        __shared__ float res[16][256];    // 16KB: [row][side*128 + h]
        const int r0 = blk * 16;

        {
            const float4* x4 = (const float4*)x;
#pragma unroll
            for (int u = 0; u < 2; u++)
                ((float4*)sx)[tid + 256 * u] = x4[r0 * 32 + tid + 256 * u];
        }
        __syncthreads();

        const int side = tid >> 7;        // 0 = L, 1 = R
        const int h = tid & 127;
        const float* Wp = W1 + (side ? (Cc * H1 + h) : h);   // stride H1
        float acc[16];
        const float init = side ? 0.f : b1[h];
#pragma unroll
        for (int r = 0; r < 16; r++) acc[r] = init;

#pragma unroll 4
        for (int c = 0; c < Cc; c += 4) {
            float w0 = __ldg(&Wp[(c + 0) * H1]);
            float w1 = __ldg(&Wp[(c + 1) * H1]);
            float w2 = __ldg(&Wp[(c + 2) * H1]);
            float w3 = __ldg(&Wp[(c + 3) * H1]);
#pragma unroll
            for (int r = 0; r < 16; r++) {
                float4 sv = *(const float4*)&sx[r][c];
                float a = acc[r];
                a = fmaf(sv.x, w0, a);
                a = fmaf(sv.y, w1, a);
                a = fmaf(sv.z, w2, a);
                a = fmaf(sv.w, w3, a);
                acc[r] = a;
            }
        }
#pragma unroll
        for (int r = 0; r < 16; r++) res[r][side * 128 + h] = acc[r];
        __syncthreads();

#pragma unroll
        for (int u = 0; u < 8; u++) {
            int idx = tid + 256 * u;      // 0..2047
            int row = idx >> 7;
            int rem = idx & 127;
            int sd = rem >> 6;
            int j = rem & 63;
            __half2 v = __floats2half2_rn(res[row][sd * 128 + 2 * j],
                                          res[row][sd * 128 + 2 * j + 1]);
            (sd ? g_aRh : g_aLh)[(size_t)(r0 + row) * 64 + slotperm(j)] = v;
        }
    } else {
        int idx = (blk - ROW_BLKS) * 256 + tid;   // 0..4095
        int n = idx >> 6;                         // 0..63
        int j = idx & 63;                         // k-pair
        g_W2h[n * 64 + slotperm(j)] =
            __floats2half2_rn(W2[(2 * j) * H2 + n], W2[(2 * j + 1) * H2 + n]);
    }
}

// ---------------------------------------------------------------------------
// Persistent pair kernel. 256 threads = 8 warps. Tile 32i x 16j = 512 pairs.
// Warp w owns m-tiles il = 4w..4w+3. nt 0..3 W2 frags live in registers.
// Double-buffered cp.async staging; one-kstep fragment pipeline.
// ---------------------------------------------------------------------------
#define AR_STRIDE 34     // uint2 per aR row (padded; 17 uint4)
#define W2_STRIDE 34     // uint2 per W2 n-row (padded)

struct SmemLayout {
    uint2 w2[H2 * W2_STRIDE];     // 17408 B
    uint2 aL[2][TI * 32];         // 2 x 8192 B (linear rows)
    uint2 aR[2][TJ * AR_STRIDE];  // 2 x 4352 B (padded rows)
    float b2s[H2];
    float w3s[H2];
};

// decode active-tile index aa (within one batch) -> it, jt  (jt >= 2it)
__device__ __forceinline__ void decode_tile(int aa, int& it, int& jt) {
    it = (int)((65.f - sqrtf(4225.f - 4.f * (float)aa)) * 0.5f);
    while ((it + 1) * (64 - it) <= aa) it++;
    while (it * (65 - it) > aa) it--;
    jt = 2 * it + (aa - it * (65 - it));
}

__global__ void __launch_bounds__(256)
pair_kernel(const float* __restrict__ b2,
            const float* __restrict__ W3,
            const float* __restrict__ b3,
            float* __restrict__ out) {
    __shared__ SmemLayout sm;

    const int tid = threadIdx.x;
    const int wid = tid >> 5;      // 0..7
    const int lane = tid & 31;
    const int p = lane >> 2;       // 0..7
    const int q = lane & 3;        // 0..3

    // stage W2 (padded rows) + biases, once
    {
        const uint2* gW2 = (const uint2*)g_W2h;
        for (int i = tid; i < H2 * 32; i += 256) {
            int r = i >> 5, c = i & 31;
            sm.w2[r * W2_STRIDE + c] = gW2[i];
        }
        if (tid < H2) {
            sm.b2s[tid] = b2[tid];
            sm.w3s[tid] = W3[tid];
        }
    }
    const float b3v = __ldg(&b3[0]);
    __syncthreads();

    // ---- zero fully-masked tiles ----
    {
        float4* out4 = (float4*)out;
        for (int m = blockIdx.x; m < NMASK; m += gridDim.x) {
            int bz = (m >= NMASK / 2);
            int mm = m - (bz ? NMASK / 2 : 0);
            int itz = (int)((1.f + sqrtf(1.f + 4.f * (float)mm)) * 0.5f);
            while (itz * (itz + 1) <= mm) itz++;
            while (itz * (itz - 1) > mm) itz--;
            int jtz = mm - itz * (itz - 1);
            if (tid < 128) {
                int r = tid >> 2, c4 = tid & 3;
                out4[(size_t)((bz << 10) + itz * TI + r) * 256 + jtz * 4 + c4] =
                    make_float4(0.f, 0.f, 0.f, 0.f);
            }
        }
    }

    // ---- persistent W2 fragments for nt 0..3 (64 regs) ----
    uint32_t w2r[8][4][2];
#pragma unroll
    for (int ks = 0; ks < 8; ks++)
#pragma unroll
        for (int ntl = 0; ntl < 4; ntl++) {
            uint2 bb = sm.w2[(ntl * 8 + p) * W2_STRIDE + 4 * ks + q];
            w2r[ks][ntl][0] = bb.x;
            w2r[ks][ntl][1] = bb.y;
        }

    const int il0 = 4 * wid;

    // staging chunk assignment (uint4 granularity)
    const int aL_dst0 = tid;            // chunks tid, tid+256 (of 512)
    const int aR_r = tid >> 4;          // 0..15
    const int aR_c = tid & 15;          // 0..15

    // cp.async issue for tile (b,i0,j0) into buffer `buf`
    auto issue_stage = [&](int buf, int b, int i0, int j0) {
        const uint4* srcL = (const uint4*)(g_aLh + ((size_t)((b << 10) + i0) << 6));
        const uint4* srcR = (const uint4*)(g_aRh + ((size_t)((b << 10) + j0) << 6));
        uint32_t dL = smem_u32(&sm.aL[buf][0]);
        uint32_t dR = smem_u32(&sm.aR[buf][0]);
        cpasync16(dL + (uint32_t)(aL_dst0 * 16), srcL + aL_dst0);
        cpasync16(dL + (uint32_t)((aL_dst0 + 256) * 16), srcL + (aL_dst0 + 256));
        cpasync16(dR + (uint32_t)((aR_r * 17 + aR_c) * 16), srcR + tid);
    };

    // prologue: prefetch first tile
    int buf = 0;
    int curB = 0, curI0 = 0, curJ0 = 0;
    {
        int a0 = blockIdx.x;
        if (a0 < NACT) {
            int b = (a0 >= HALF_ACT);
            int aa = a0 - (b ? HALF_ACT : 0);
            int it, jt;
            decode_tile(aa, it, jt);
            curB = b; curI0 = it * TI; curJ0 = jt * TJ;
            issue_stage(0, curB, curI0, curJ0);
        }
        CP_COMMIT();
    }

    for (int a = blockIdx.x; a < NACT; a += gridDim.x) {
        const int b  = curB;
        const int i0 = curI0;
        const int j0 = curJ0;

        // prefetch next tile into the other buffer
        {
            int an = a + gridDim.x;
            if (an < NACT) {
                int bn = (an >= HALF_ACT);
                int aan = an - (bn ? HALF_ACT : 0);
                int itn, jtn;
                decode_tile(aan, itn, jtn);
                curB = bn; curI0 = itn * TI; curJ0 = jtn * TJ;
                issue_stage(buf ^ 1, bn, curI0, curJ0);
            }
            CP_COMMIT();
        }
        CP_WAIT1();          // all but the just-committed group complete
        __syncthreads();     // current buffer visible to all warps

        const uint2* aLb = sm.aL[buf];
        const uint2* aRb = sm.aR[buf];

        float acc[4][8][4];
#pragma unroll
        for (int mt = 0; mt < 4; mt++)
#pragma unroll
            for (int nt = 0; nt < 8; nt++)
#pragma unroll
                for (int e = 0; e < 4; e++) acc[mt][nt][e] = 0.f;

        // ---- kstep loop with one-stage register pipeline ----
        uint2 Rp_c, Rp8_c, La_c0, La_c1, La_c2, La_c3;
        {
            const int kf = q;
            Rp_c  = aRb[p * AR_STRIDE + kf];
            Rp8_c = aRb[(p + 8) * AR_STRIDE + kf];
            La_c0 = aLb[(il0 + 0) * 32 + kf];
            La_c1 = aLb[(il0 + 1) * 32 + kf];
            La_c2 = aLb[(il0 + 2) * 32 + kf];
            La_c3 = aLb[(il0 + 3) * 32 + kf];
        }
#pragma unroll
        for (int ks = 0; ks < 8; ks++) {
            uint2 Rp_n, Rp8_n, La_n0, La_n1, La_n2, La_n3;
            if (ks < 7) {
                const int kf = 4 * (ks + 1) + q;
                Rp_n  = aRb[p * AR_STRIDE + kf];
                Rp8_n = aRb[(p + 8) * AR_STRIDE + kf];
                La_n0 = aLb[(il0 + 0) * 32 + kf];
                La_n1 = aLb[(il0 + 1) * 32 + kf];
                La_n2 = aLb[(il0 + 2) * 32 + kf];
                La_n3 = aLb[(il0 + 3) * 32 + kf];
            }

            uint32_t a4[4][4];
            {
                uint2 Ls[4] = {La_c0, La_c1, La_c2, La_c3};
#pragma unroll
                for (int mt = 0; mt < 4; mt++) {
                    a4[mt][0] = h2_relu_add(Ls[mt].x, Rp_c.x);
                    a4[mt][1] = h2_relu_add(Ls[mt].x, Rp8_c.x);
                    a4[mt][2] = h2_relu_add(Ls[mt].y, Rp_c.y);
                    a4[mt][3] = h2_relu_add(Ls[mt].y, Rp8_c.y);
                }
            }

            // nt 0..3 from registers
#pragma unroll
            for (int ntl = 0; ntl < 4; ntl++)
#pragma unroll
                for (int mt = 0; mt < 4; mt++)
                    mma_f16(acc[mt][ntl], a4[mt],
                            w2r[ks][ntl][0], w2r[ks][ntl][1]);
            // nt 4..7 from smem
#pragma unroll
            for (int ntl = 4; ntl < 8; ntl++) {
                uint2 bb = sm.w2[(ntl * 8 + p) * W2_STRIDE + 4 * ks + q];
#pragma unroll
                for (int mt = 0; mt < 4; mt++)
                    mma_f16(acc[mt][ntl], a4[mt], bb.x, bb.y);
            }

            Rp_c = Rp_n; Rp8_c = Rp8_n;
            La_c0 = La_n0; La_c1 = La_n1; La_c2 = La_n2; La_c3 = La_n3;
        }

        // ---- epilogue: y = b3 + sum_g relu(D+b2)*W3 ; quad reduction ----
#pragma unroll
        for (int mt = 0; mt < 4; mt++) {
            float slo = 0.f, shi = 0.f;
#pragma unroll
            for (int nt = 0; nt < 8; nt++) {
                int g0 = nt * 8 + 2 * q;
                float b20 = sm.b2s[g0], b21 = sm.b2s[g0 + 1];
                float w30 = sm.w3s[g0], w31 = sm.w3s[g0 + 1];
                slo = fmaf(fmaxf(acc[mt][nt][0] + b20, 0.f), w30, slo);
                slo = fmaf(fmaxf(acc[mt][nt][1] + b21, 0.f), w31, slo);
                shi = fmaf(fmaxf(acc[mt][nt][2] + b20, 0.f), w30, shi);
                shi = fmaf(fmaxf(acc[mt][nt][3] + b21, 0.f), w31, shi);
            }
            slo += __shfl_xor_sync(0xFFFFFFFFu, slo, 1);
            slo += __shfl_xor_sync(0xFFFFFFFFu, slo, 2);
            shi += __shfl_xor_sync(0xFFFFFFFFu, shi, 1);
            shi += __shfl_xor_sync(0xFFFFFFFFu, shi, 2);
            if (q == 0) {
                int gi = i0 + il0 + mt;
                int gjlo = j0 + p;
                int gjhi = gjlo + 8;
                size_t base = ((size_t)((b << 10) + gi)) << 10;
                out[base + gjlo] = (gjlo > gi) ? (slo + b3v) : 0.f;
                out[base + gjhi] = (gjhi > gi) ? (shi + b3v) : 0.f;
            }
        }
        __syncthreads();   // all reads of `buf` done before it is re-staged
        buf ^= 1;
    }
}

// ---------------------------------------------------------------------------
extern "C" void kernel_launch(void* const* d_in, const int* in_sizes, int n_in,
                              void* d_out, int out_size) {
    const float* x  = (const float*)d_in[0];
    const float* W1 = (const float*)d_in[1];
    const float* b1 = (const float*)d_in[2];
    const float* W2 = (const float*)d_in[3];
    const float* b2 = (const float*)d_in[4];
    const float* W3 = (const float*)d_in[5];
    const float* b3 = (const float*)d_in[6];
    float* out = (float*)d_out;

    prep_kernel<<<PREP_GRID, 256>>>(x, W1, b1, W2);
    pair_kernel<<<152, 256>>>(b2, W3, b3, out);
}